// round 9
// baseline (speedup 1.0000x reference)
#include <cuda_runtime.h>
#include <cuda_bf16.h>
#include <cstdint>

namespace {
constexpr int H=448, Wd=608, K=32, Bn=2, TPB=256, PXT=128, WT=5;
constexpr int XS=72;                       // bf16 row stride (144B = 9*16B)
constexpr int XSPL=128*XS*2;               // 18432 per activation split
constexpr int WSPL=64*XS*2;                // 9216 per 64-row weight split
constexpr int W3SPL=32*XS*2;               // 4608
constexpr int SM_B1=0, SM_B2=256, SM_B3=512, SM_BR=640;
constexpr int SM_PV=1024;                  // 2*128 f32 argmax vals
constexpr int SM_PI=2048;                  // 2*128 i32 argmax idx
constexpr int SM_X =3072;                  // X splits x3 (Y1 overlays after Dr)
constexpr int SM_Y0=SM_X+3*XSPL;           // 58368 (Dr f32 overlay after L2)
constexpr int SM_W1=SM_Y0+3*XSPL;          // 113664
constexpr int SM_W2=SM_W1+3*WSPL;          // 141312
constexpr int SM_W3=SM_W2+3*WSPL;          // 168960
constexpr int SM_WR=SM_W3+3*W3SPL;         // 182784
constexpr int SMEM_BYTES=SM_WR+2*WSPL;     // 201216
constexpr int SM_DR=SM_Y0;
constexpr int DRS=66;
}

__device__ __forceinline__ float lrelu(float v){ return v>=0.f ? v : 0.01f*v; }
__device__ __forceinline__ uint32_t smem_u32(const void* p){
    uint32_t a;
    asm("{ .reg .u64 t; cvta.to.shared.u64 t, %1; cvt.u32.u64 %0, t; }" : "=r"(a) : "l"(p));
    return a;
}
__device__ __forceinline__ void sts32(uint32_t a, uint32_t v){
    asm volatile("st.shared.b32 [%0], %1;" :: "r"(a), "r"(v) : "memory");
}
__device__ __forceinline__ void ldsm4(uint32_t addr, uint32_t* r){
    asm volatile("ldmatrix.sync.aligned.m8n8.x4.shared.b16 {%0,%1,%2,%3}, [%4];"
                 : "=r"(r[0]), "=r"(r[1]), "=r"(r[2]), "=r"(r[3]) : "r"(addr));
}
__device__ __forceinline__ void mma_bf16(float d[4], const uint32_t a[4], uint32_t b0, uint32_t b1){
    asm volatile("mma.sync.aligned.m16n8k16.row.col.f32.bf16.bf16.f32 "
                 "{%0,%1,%2,%3},{%4,%5,%6,%7},{%8,%9},{%0,%1,%2,%3};"
                 : "+f"(d[0]), "+f"(d[1]), "+f"(d[2]), "+f"(d[3])
                 : "r"(a[0]), "r"(a[1]), "r"(a[2]), "r"(a[3]), "r"(b0), "r"(b1));
}
__device__ __forceinline__ uint32_t hb(__nv_bfloat16 h){
    return (uint32_t)reinterpret_cast<const uint16_t&>(h);
}
// exact residual splits: v = s0 + s1 + s2 (+eps ~2^-27|v|)
__device__ __forceinline__ void split3pair(float a, float b, uint32_t s[3]){
    __nv_bfloat16 a0=__float2bfloat16_rn(a); float ra=a-__bfloat162float(a0);
    __nv_bfloat16 a1=__float2bfloat16_rn(ra);
    __nv_bfloat16 a2=__float2bfloat16_rn(ra-__bfloat162float(a1));
    __nv_bfloat16 b0=__float2bfloat16_rn(b); float rb=b-__bfloat162float(b0);
    __nv_bfloat16 b1=__float2bfloat16_rn(rb);
    __nv_bfloat16 b2=__float2bfloat16_rn(rb-__bfloat162float(b1));
    s[0]=hb(a0)|(hb(b0)<<16); s[1]=hb(a1)|(hb(b1)<<16); s[2]=hb(a2)|(hb(b2)<<16);
}
__device__ __forceinline__ void split2pair(float a, float b, uint32_t s[2]){
    __nv_bfloat16 a0=__float2bfloat16_rn(a);
    __nv_bfloat16 a1=__float2bfloat16_rn(a-__bfloat162float(a0));
    __nv_bfloat16 b0=__float2bfloat16_rn(b);
    __nv_bfloat16 b1=__float2bfloat16_rn(b-__bfloat162float(b0));
    s[0]=hb(a0)|(hb(b0)<<16); s[1]=hb(a1)|(hb(b1)<<16);
}

// Multi-pass emulated GEMM. aB/bB are lane-resolved ldmatrix base addrs.
// NT n8-tiles per warp; NA/NB split counts; NP passes from pass table.
template<int NT,int NA,int NB,int NP>
__device__ __forceinline__ void gemm_emu(uint32_t aB, uint32_t bB, int bSpl, float D[2*NT][4]){
    #pragma unroll
    for(int i=0;i<2*NT;++i){ D[i][0]=D[i][1]=D[i][2]=D[i][3]=0.f; }
    constexpr int PA[6]={0,0,1,0,1,2};
    constexpr int PB[6]={0,1,0,2,1,0};
    #pragma unroll 1
    for(int ks=0;ks<4;++ks){
        uint32_t a[NA][2][4];
        #pragma unroll
        for(int s=0;s<NA;++s){
            ldsm4(aB+s*XSPL+ks*32, a[s][0]);
            ldsm4(aB+s*XSPL+16*XS*2+ks*32, a[s][1]);
        }
        uint32_t bf[NB][NT/2][4];
        #pragma unroll
        for(int s=0;s<NB;++s)
            #pragma unroll
            for(int n2=0;n2<NT/2;++n2)
                ldsm4(bB+s*bSpl+n2*16*XS*2+ks*32, bf[s][n2]);
        #pragma unroll
        for(int p=0;p<NP;++p)
            #pragma unroll
            for(int mt=0;mt<2;++mt)
                #pragma unroll
                for(int nt=0;nt<NT;++nt)
                    mma_bf16(D[mt*NT+nt], a[PA[p]][mt],
                             bf[PB[p]][nt>>1][(nt&1)*2], bf[PB[p]][nt>>1][(nt&1)*2+1]);
    }
}

// bias + lrelu + 3-split bf16 store (activation layout, warp covers 32px x 32n)
__device__ __forceinline__ void epi_split(float D[8][4], const float* __restrict__ bias,
                                          uint32_t outB, int wm, int wn, int lane){
    const int g=lane>>2, c2=2*(lane&3);
    #pragma unroll
    for(int mt=0;mt<2;++mt)
        #pragma unroll
        for(int nt=0;nt<4;++nt){
            const int n0=wn*32+nt*8+c2;
            const float bv0=bias[n0], bv1=bias[n0+1];
            const float* d=D[mt*4+nt];
            uint32_t s[3];
            const uint32_t a0=outB+((wm*32+mt*16+g)*XS+n0)*2;
            split3pair(lrelu(d[0]+bv0), lrelu(d[1]+bv1), s);
            sts32(a0,s[0]); sts32(a0+XSPL,s[1]); sts32(a0+2*XSPL,s[2]);
            const uint32_t a1=a0+8*XS*2;
            split3pair(lrelu(d[2]+bv0), lrelu(d[3]+bv1), s);
            sts32(a1,s[0]); sts32(a1+XSPL,s[1]); sts32(a1+2*XSPL,s[2]);
        }
}

__global__ void __launch_bounds__(TPB,1)
reg1stage_emu(const float* __restrict__ x,
              const float* __restrict__ W1g, const float* __restrict__ b1g,
              const float* __restrict__ W2g, const float* __restrict__ b2g,
              const float* __restrict__ W3g, const float* __restrict__ b3g,
              const float* __restrict__ Wr,  const float* __restrict__ br,
              float* __restrict__ out)
{
    extern __shared__ char smem[];
    const uint32_t sb = smem_u32(smem);
    float* smf = reinterpret_cast<float*>(smem);
    float* spv = reinterpret_cast<float*>(smem+SM_PV);
    int*   spi = reinterpret_cast<int*>(smem+SM_PI);
    const int tid=threadIdx.x, lane=tid&31, warp=tid>>5;
    const int wm=warp>>1, wn=warp&1;
    const int h=blockIdx.x, b=blockIdx.y;

    // ---- stage weights: fp32 -> bf16 splits ----
    {
        const float* g1=W1g+h*4096;
        const float* g2=W2g+h*4096;
        #pragma unroll
        for(int i=0;i<8;++i){
            const int p=tid+i*TPB;                 // pair 0..2047
            const int n=p>>5, c0=(p&31)*2;
            uint32_t s[3];
            const float2 v1=*reinterpret_cast<const float2*>(g1+n*64+c0);
            split3pair(v1.x,v1.y,s);
            uint32_t a=sb+SM_W1+(n*XS+c0)*2;
            sts32(a,s[0]); sts32(a+WSPL,s[1]); sts32(a+2*WSPL,s[2]);
            const float2 v2=*reinterpret_cast<const float2*>(g2+n*64+c0);
            split3pair(v2.x,v2.y,s);
            a=sb+SM_W2+(n*XS+c0)*2;
            sts32(a,s[0]); sts32(a+WSPL,s[1]); sts32(a+2*WSPL,s[2]);
        }
        const float* g3=W3g+h*2048;
        #pragma unroll
        for(int i=0;i<4;++i){
            const int p=tid+i*TPB;                 // pair 0..1023
            const int n=p>>5, c0=(p&31)*2;
            uint32_t s[3];
            const float2 v=*reinterpret_cast<const float2*>(g3+n*64+c0);
            split3pair(v.x,v.y,s);
            const uint32_t a=sb+SM_W3+(n*XS+c0)*2;
            sts32(a,s[0]); sts32(a+W3SPL,s[1]); sts32(a+2*W3SPL,s[2]);
        }
        // Wr [(h*K+k)][c][2] -> row n=2k+o, col c; 2 splits
        const float* gr=Wr+(size_t)(h*K)*128;
        const int n=tid>>2, k=n>>1, o=n&1;
        #pragma unroll
        for(int j=0;j<16;j+=2){
            const int c=(tid&3)*16+j;
            const float va=gr[k*128+c*2+o];
            const float vb=gr[k*128+(c+1)*2+o];
            uint32_t s[2];
            split2pair(va,vb,s);
            const uint32_t a=sb+SM_WR+(n*XS+c)*2;
            sts32(a,s[0]); sts32(a+WSPL,s[1]);
        }
        if(tid<64){
            smf[SM_B1/4+tid]=b1g[h*64+tid];
            smf[SM_B2/4+tid]=b2g[h*64+tid];
            smf[SM_BR/4+tid]=br[h*64+tid];
        }
        if(tid<32) smf[SM_B3/4+tid]=b3g[h*32+tid];
    }

    const size_t HW=(size_t)H*Wd;
    const float* xbase=x+(size_t)b*64*HW+(size_t)h*Wd;
    const int pix_base=(b*H+h)*Wd;
    const int plane=Bn*H*Wd;
    const float inv_k=1.0f/(float)K;

    // lane-resolved ldmatrix bases
    const uint32_t aRel=((wm*32+(lane&15))*XS+(lane>>4)*8)*2;
    const uint32_t bRel=(((lane>>4)*8+(lane&7))*XS+((lane>>3)&1)*8)*2;
    const uint32_t aX =sb+SM_X +aRel;
    const uint32_t aY0=sb+SM_Y0+aRel;
    const uint32_t bW1=sb+SM_W1+bRel+(wn*32)*XS*2;
    const uint32_t bW2=sb+SM_W2+bRel+(wn*32)*XS*2;
    const uint32_t bW3=sb+SM_W3+bRel+(wn*16)*XS*2;
    const uint32_t bWR=sb+SM_WR+bRel+(wn*32)*XS*2;

    __syncthreads();

    for(int wt=0;wt<WT;++wt){
        const int w0=wt*PXT;

        // ---- stage X: fp32 -> 3 bf16 splits ----
        {
            const int px=tid&127, ch0=(tid>>7)*32;
            const int wcl=min(w0+px, Wd-1);
            const float* xp=xbase+wcl;
            #pragma unroll
            for(int j=0;j<16;++j){
                const int c=ch0+2*j;
                const float va=__ldg(xp+(size_t)c*HW);
                const float vb=__ldg(xp+(size_t)(c+1)*HW);
                uint32_t s[3];
                split3pair(va,vb,s);
                const uint32_t a=sb+SM_X+(px*XS+c)*2;
                sts32(a,s[0]); sts32(a+XSPL,s[1]); sts32(a+2*XSPL,s[2]);
            }
        }
        __syncthreads();

        // ---- L1: Y0 = lrelu(X.W1^T+b1), 6-pass ----
        {
            float D1[8][4];
            gemm_emu<4,3,3,6>(aX,bW1,WSPL,D1);
            epi_split(D1, smf+SM_B1/4, sb+SM_Y0, wm, wn, lane);
        }
        // ---- Dr = X.Wr^T, 3-pass, kept in regs across L2 ----
        float Dr[8][4];
        gemm_emu<4,2,2,3>(aX,bWR,WSPL,Dr);
        __syncthreads();            // Y0 published; X reads done

        // ---- L2: Y1 = lrelu(Y0.W2^T+b2) -> overlays X ----
        {
            float D2[8][4];
            gemm_emu<4,3,3,6>(aY0,bW2,WSPL,D2);
            epi_split(D2, smf+SM_B2/4, sb+SM_X, wm, wn, lane);
        }
        __syncthreads();            // Y1 published; Y0 reads done

        // ---- L3: cls = Y1.W3^T+b3 (6-pass) -> warp-local argmax partials ----
        {
            float D3[4][4];
            gemm_emu<2,3,3,6>(aX,bW3,W3SPL,D3);
            const float* b3s=smf+SM_B3/4;
            const int g=lane>>2, c2=2*(lane&3);
            #pragma unroll
            for(int mt=0;mt<2;++mt){
                float bestA=-3.402823466e38f, bestB=-3.402823466e38f;
                int nA=0, nB=0;
                #pragma unroll
                for(int nt=0;nt<2;++nt){
                    const int n0=wn*16+nt*8+c2;
                    const float bv0=b3s[n0], bv1=b3s[n0+1];
                    const float* d=D3[mt*2+nt];
                    const float vA0=d[0]+bv0, vA1=d[1]+bv1;
                    const float vB0=d[2]+bv0, vB1=d[3]+bv1;
                    if(vA0>bestA){bestA=vA0;nA=n0;}
                    if(vA1>bestA){bestA=vA1;nA=n0+1;}
                    if(vB0>bestB){bestB=vB0;nB=n0;}
                    if(vB1>bestB){bestB=vB1;nB=n0+1;}
                }
                #pragma unroll
                for(int m=1;m<=2;m<<=1){
                    const float ovA=__shfl_xor_sync(0xFFFFFFFFu,bestA,m);
                    const int   onA=__shfl_xor_sync(0xFFFFFFFFu,nA,m);
                    if(ovA>bestA||(ovA==bestA&&onA<nA)){bestA=ovA;nA=onA;}
                    const float ovB=__shfl_xor_sync(0xFFFFFFFFu,bestB,m);
                    const int   onB=__shfl_xor_sync(0xFFFFFFFFu,nB,m);
                    if(ovB>bestB||(ovB==bestB&&onB<nB)){bestB=ovB;nB=onB;}
                }
                if((lane&3)==0){
                    const int r=wm*32+mt*16+g;
                    spv[wn*128+r]=bestA;   spi[wn*128+r]=nA;
                    spv[wn*128+r+8]=bestB; spi[wn*128+r+8]=nB;
                }
            }
            // ---- spill Dr (f32) into freed Y0 region ----
            float* dr=reinterpret_cast<float*>(smem+SM_DR);
            #pragma unroll
            for(int mt=0;mt<2;++mt)
                #pragma unroll
                for(int nt=0;nt<4;++nt){
                    const int n0=wn*32+nt*8+c2;
                    const float* d=Dr[mt*4+nt];
                    *reinterpret_cast<float2*>(dr+(wm*32+mt*16+g)*DRS+n0)  =make_float2(d[0],d[1]);
                    *reinterpret_cast<float2*>(dr+(wm*32+mt*16+g+8)*DRS+n0)=make_float2(d[2],d[3]);
                }
        }
        __syncthreads();

        // ---- tail ----
        if(tid<128){
            const int px=tid, wc=w0+px;
            if(wc<Wd){
                const float v0=spv[px], v1=spv[128+px];
                const int   i0=spi[px], i1=spi[128+px];
                const int bk=(v1>v0)?i1:i0;     // i0 classes 0-15 < i1: tie -> lower ✓
                const float* dr=reinterpret_cast<const float*>(smem+SM_DR);
                const float2 dv=*reinterpret_cast<const float2*>(dr+px*DRS+2*bk);
                const float reg0=lrelu(dv.x+smf[SM_BR/4+2*bk]);
                const float reg1=lrelu(dv.y+smf[SM_BR/4+2*bk+1]);
                const int flat=h*K+bk;
                out[pix_base+wc]      =((float)flat+reg0)*inv_k;
                out[plane+pix_base+wc]=lrelu(reg1);
            }
        }
        __syncthreads();            // dr/spv reads done before next tile
    }
}

extern "C" void kernel_launch(void* const* d_in, const int* in_sizes, int n_in,
                              void* d_out, int out_size)
{
    const float* x =(const float*)d_in[0];
    const float* W1=(const float*)d_in[1];
    const float* b1=(const float*)d_in[2];
    const float* W2=(const float*)d_in[3];
    const float* b2=(const float*)d_in[4];
    const float* W3=(const float*)d_in[5];
    const float* b3=(const float*)d_in[6];
    const float* Wr=(const float*)d_in[7];
    const float* br=(const float*)d_in[8];
    float* out=(float*)d_out;

    cudaFuncSetAttribute(reg1stage_emu,
                         cudaFuncAttributeMaxDynamicSharedMemorySize, SMEM_BYTES);
    dim3 grid(H,Bn);
    reg1stage_emu<<<grid,TPB,SMEM_BYTES>>>(x,W1,b1,W2,b2,W3,b3,Wr,br,out);
}

// round 10
// speedup vs baseline: 1.0131x; 1.0131x over previous
#include <cuda_runtime.h>
#include <cuda_bf16.h>
#include <cstdint>

namespace {
constexpr int H=448, Wd=608, K=32, Bn=2, TPB=512, PXT=128, WT=5;
constexpr int XS=72;                       // bf16 row stride (144B = 9*16B)
constexpr int XSPL=128*XS*2;               // 18432 per activation split
constexpr int WSPL=64*XS*2;                // 9216 per 64-row weight split
constexpr int W3SPL=32*XS*2;               // 4608
constexpr int SM_B1=0, SM_B2=256, SM_B3=512, SM_BR=640;
constexpr int SM_PV=1024;                  // 2*128 f32 argmax vals
constexpr int SM_PI=2048;                  // 2*128 i32 argmax idx
constexpr int SM_X =3072;                  // X splits x3 (Y1 overlays after Dr)
constexpr int SM_Y0=SM_X+3*XSPL;           // 58368 (Dr f32 overlay after L2)
constexpr int SM_W1=SM_Y0+3*XSPL;          // 113664
constexpr int SM_W2=SM_W1+3*WSPL;          // 141312
constexpr int SM_W3=SM_W2+3*WSPL;          // 168960
constexpr int SM_WR=SM_W3+3*W3SPL;         // 182784
constexpr int SMEM_BYTES=SM_WR+2*WSPL;     // 201216
constexpr int SM_DR=SM_Y0;
constexpr int DRS=66;
}

__device__ __forceinline__ float lrelu(float v){ return v>=0.f ? v : 0.01f*v; }
__device__ __forceinline__ uint32_t smem_u32(const void* p){
    uint32_t a;
    asm("{ .reg .u64 t; cvta.to.shared.u64 t, %1; cvt.u32.u64 %0, t; }" : "=r"(a) : "l"(p));
    return a;
}
__device__ __forceinline__ void sts32(uint32_t a, uint32_t v){
    asm volatile("st.shared.b32 [%0], %1;" :: "r"(a), "r"(v) : "memory");
}
__device__ __forceinline__ void ldsm4(uint32_t addr, uint32_t* r){
    asm volatile("ldmatrix.sync.aligned.m8n8.x4.shared.b16 {%0,%1,%2,%3}, [%4];"
                 : "=r"(r[0]), "=r"(r[1]), "=r"(r[2]), "=r"(r[3]) : "r"(addr));
}
__device__ __forceinline__ void mma_bf16(float d[4], const uint32_t a[4], uint32_t b0, uint32_t b1){
    asm volatile("mma.sync.aligned.m16n8k16.row.col.f32.bf16.bf16.f32 "
                 "{%0,%1,%2,%3},{%4,%5,%6,%7},{%8,%9},{%0,%1,%2,%3};"
                 : "+f"(d[0]), "+f"(d[1]), "+f"(d[2]), "+f"(d[3])
                 : "r"(a[0]), "r"(a[1]), "r"(a[2]), "r"(a[3]), "r"(b0), "r"(b1));
}
__device__ __forceinline__ uint32_t hb(__nv_bfloat16 h){
    return (uint32_t)reinterpret_cast<const uint16_t&>(h);
}
// exact residual splits: v = s0+s1+s2 (+eps ~2^-27|v|)
__device__ __forceinline__ void split3pair(float a, float b, uint32_t s[3]){
    __nv_bfloat16 a0=__float2bfloat16_rn(a); float ra=a-__bfloat162float(a0);
    __nv_bfloat16 a1=__float2bfloat16_rn(ra);
    __nv_bfloat16 a2=__float2bfloat16_rn(ra-__bfloat162float(a1));
    __nv_bfloat16 b0=__float2bfloat16_rn(b); float rb=b-__bfloat162float(b0);
    __nv_bfloat16 b1=__float2bfloat16_rn(rb);
    __nv_bfloat16 b2=__float2bfloat16_rn(rb-__bfloat162float(b1));
    s[0]=hb(a0)|(hb(b0)<<16); s[1]=hb(a1)|(hb(b1)<<16); s[2]=hb(a2)|(hb(b2)<<16);
}
__device__ __forceinline__ void split2pair(float a, float b, uint32_t s[2]){
    __nv_bfloat16 a0=__float2bfloat16_rn(a);
    __nv_bfloat16 a1=__float2bfloat16_rn(a-__bfloat162float(a0));
    __nv_bfloat16 b0=__float2bfloat16_rn(b);
    __nv_bfloat16 b1=__float2bfloat16_rn(b-__bfloat162float(b0));
    s[0]=hb(a0)|(hb(b0)<<16); s[1]=hb(a1)|(hb(b1)<<16);
}

// Emulated GEMM, warp tile 32px x 16n (NT=2). aB/bB lane-resolved ldmatrix bases.
// NA/NB split counts, NP passes.
template<int NA,int NB,int NP>
__device__ __forceinline__ void gemm_emu2(uint32_t aB, uint32_t bB, int bSpl, float D[4][4]){
    #pragma unroll
    for(int i=0;i<4;++i){ D[i][0]=D[i][1]=D[i][2]=D[i][3]=0.f; }
    constexpr int PA[6]={0,0,1,0,1,2};
    constexpr int PB[6]={0,1,0,2,1,0};
    #pragma unroll 1
    for(int ks=0;ks<4;++ks){
        uint32_t a[NA][2][4];
        #pragma unroll
        for(int s=0;s<NA;++s){
            ldsm4(aB+s*XSPL+ks*32, a[s][0]);
            ldsm4(aB+s*XSPL+16*XS*2+ks*32, a[s][1]);
        }
        uint32_t bf[NB][4];
        #pragma unroll
        for(int s=0;s<NB;++s)
            ldsm4(bB+s*bSpl+ks*32, bf[s]);
        #pragma unroll
        for(int p=0;p<NP;++p)
            #pragma unroll
            for(int mt=0;mt<2;++mt)
                #pragma unroll
                for(int nt=0;nt<2;++nt)
                    mma_bf16(D[mt*2+nt], a[PA[p]][mt],
                             bf[PB[p]][nt*2], bf[PB[p]][nt*2+1]);
    }
}

// bias + lrelu + 3-split bf16 store; warp covers 32px x 16n
__device__ __forceinline__ void epi_split(float D[4][4], const float* __restrict__ bias,
                                          uint32_t outB, int wm, int wn, int lane){
    const int g=lane>>2, c2=2*(lane&3);
    #pragma unroll
    for(int mt=0;mt<2;++mt)
        #pragma unroll
        for(int nt=0;nt<2;++nt){
            const int n0=wn*16+nt*8+c2;
            const float bv0=bias[n0], bv1=bias[n0+1];
            const float* d=D[mt*2+nt];
            uint32_t s[3];
            const uint32_t a0=outB+((wm*32+mt*16+g)*XS+n0)*2;
            split3pair(lrelu(d[0]+bv0), lrelu(d[1]+bv1), s);
            sts32(a0,s[0]); sts32(a0+XSPL,s[1]); sts32(a0+2*XSPL,s[2]);
            const uint32_t a1=a0+8*XS*2;
            split3pair(lrelu(d[2]+bv0), lrelu(d[3]+bv1), s);
            sts32(a1,s[0]); sts32(a1+XSPL,s[1]); sts32(a1+2*XSPL,s[2]);
        }
}

__global__ void __launch_bounds__(TPB,1)
reg1stage_emu(const float* __restrict__ x,
              const float* __restrict__ W1g, const float* __restrict__ b1g,
              const float* __restrict__ W2g, const float* __restrict__ b2g,
              const float* __restrict__ W3g, const float* __restrict__ b3g,
              const float* __restrict__ Wr,  const float* __restrict__ br,
              float* __restrict__ out)
{
    extern __shared__ char smem[];
    const uint32_t sb = smem_u32(smem);
    float* smf = reinterpret_cast<float*>(smem);
    float* spv = reinterpret_cast<float*>(smem+SM_PV);
    int*   spi = reinterpret_cast<int*>(smem+SM_PI);
    const int tid=threadIdx.x, lane=tid&31, warp=tid>>5;
    const int wm=warp>>2, wn=warp&3;        // 4x4 warp grid
    const int h=blockIdx.x, b=blockIdx.y;

    // ---- stage weights: fp32 -> bf16 splits ----
    {
        const float* g1=W1g+h*4096;
        const float* g2=W2g+h*4096;
        #pragma unroll
        for(int i=0;i<4;++i){
            const int p=tid+i*TPB;                 // pair 0..2047
            const int n=p>>5, c0=(p&31)*2;
            uint32_t s[3];
            const float2 v1=*reinterpret_cast<const float2*>(g1+n*64+c0);
            split3pair(v1.x,v1.y,s);
            uint32_t a=sb+SM_W1+(n*XS+c0)*2;
            sts32(a,s[0]); sts32(a+WSPL,s[1]); sts32(a+2*WSPL,s[2]);
            const float2 v2=*reinterpret_cast<const float2*>(g2+n*64+c0);
            split3pair(v2.x,v2.y,s);
            a=sb+SM_W2+(n*XS+c0)*2;
            sts32(a,s[0]); sts32(a+WSPL,s[1]); sts32(a+2*WSPL,s[2]);
        }
        const float* g3=W3g+h*2048;
        #pragma unroll
        for(int i=0;i<2;++i){
            const int p=tid+i*TPB;                 // pair 0..1023
            const int n=p>>5, c0=(p&31)*2;
            uint32_t s[3];
            const float2 v=*reinterpret_cast<const float2*>(g3+n*64+c0);
            split3pair(v.x,v.y,s);
            const uint32_t a=sb+SM_W3+(n*XS+c0)*2;
            sts32(a,s[0]); sts32(a+W3SPL,s[1]); sts32(a+2*W3SPL,s[2]);
        }
        // Wr [(h*K+k)][c][2] -> row n=2k+o, col c; 2 splits
        const float* gr=Wr+(size_t)(h*K)*128;
        const int n=tid>>3, k=n>>1, o=n&1;
        #pragma unroll
        for(int j=0;j<4;++j){
            const int c=2*((tid&7)+j*8);           // even c 0..62
            const float va=gr[k*128+c*2+o];
            const float vb=gr[k*128+(c+1)*2+o];
            uint32_t s[2];
            split2pair(va,vb,s);
            const uint32_t a=sb+SM_WR+(n*XS+c)*2;
            sts32(a,s[0]); sts32(a+WSPL,s[1]);
        }
        if(tid<64){
            smf[SM_B1/4+tid]=b1g[h*64+tid];
            smf[SM_B2/4+tid]=b2g[h*64+tid];
            smf[SM_BR/4+tid]=br[h*64+tid];
        }
        if(tid<32) smf[SM_B3/4+tid]=b3g[h*32+tid];
    }

    const size_t HW=(size_t)H*Wd;
    const float* xbase=x+(size_t)b*64*HW+(size_t)h*Wd;
    const int pix_base=(b*H+h)*Wd;
    const int plane=Bn*H*Wd;
    const float inv_k=1.0f/(float)K;

    // lane-resolved ldmatrix bases
    const uint32_t aRel=((wm*32+(lane&15))*XS+(lane>>4)*8)*2;
    const uint32_t bRel=(((lane>>4)*8+(lane&7))*XS+((lane>>3)&1)*8)*2;
    const uint32_t aX =sb+SM_X +aRel;
    const uint32_t aY0=sb+SM_Y0+aRel;
    const uint32_t bW1=sb+SM_W1+bRel+(wn*16)*XS*2;
    const uint32_t bW2=sb+SM_W2+bRel+(wn*16)*XS*2;
    const uint32_t bW3=sb+SM_W3+bRel+(wn*16)*XS*2;   // wn<2 only
    const uint32_t bWR=sb+SM_WR+bRel+(wn*16)*XS*2;

    __syncthreads();

    for(int wt=0;wt<WT;++wt){
        const int w0=wt*PXT;

        // ---- stage X: fp32 -> 3 bf16 splits (512 threads, 8 pairs each) ----
        {
            const int px=tid&127, c0=(tid>>7)*16;
            const int wcl=min(w0+px, Wd-1);
            const float* xp=xbase+wcl;
            #pragma unroll
            for(int j=0;j<8;++j){
                const int c=c0+2*j;
                const float va=__ldg(xp+(size_t)c*HW);
                const float vb=__ldg(xp+(size_t)(c+1)*HW);
                uint32_t s[3];
                split3pair(va,vb,s);
                const uint32_t a=sb+SM_X+(px*XS+c)*2;
                sts32(a,s[0]); sts32(a+XSPL,s[1]); sts32(a+2*XSPL,s[2]);
            }
        }
        __syncthreads();

        // ---- L1: Y0 = lrelu(X.W1^T+b1), 3-split 6-pass ----
        {
            float D1[4][4];
            gemm_emu2<3,3,6>(aX,bW1,WSPL,D1);
            epi_split(D1, smf+SM_B1/4, sb+SM_Y0, wm, wn, lane);
        }
        // ---- Dr = X.Wr^T, 2-split 3-pass, kept in regs across L2 ----
        float Dr[4][4];
        gemm_emu2<2,2,3>(aX,bWR,WSPL,Dr);
        __syncthreads();            // Y0 published; X reads done

        // ---- L2: Y1 = lrelu(Y0.W2^T+b2) -> overlays X ----
        {
            float D2[4][4];
            gemm_emu2<3,3,6>(aY0,bW2,WSPL,D2);
            epi_split(D2, smf+SM_B2/4, sb+SM_X, wm, wn, lane);
        }
        __syncthreads();            // Y1 published; Y0 reads done

        // ---- L3 (warps wn<2): cls = Y1.W3^T+b3 -> argmax partials ----
        if(wn<2){
            float D3[4][4];
            gemm_emu2<3,3,6>(aX,bW3,W3SPL,D3);
            const float* b3s=smf+SM_B3/4;
            const int g=lane>>2, c2=2*(lane&3);
            #pragma unroll
            for(int mt=0;mt<2;++mt){
                float bestA=-3.402823466e38f, bestB=-3.402823466e38f;
                int nA=0, nB=0;
                #pragma unroll
                for(int nt=0;nt<2;++nt){
                    const int n0=wn*16+nt*8+c2;
                    const float bv0=b3s[n0], bv1=b3s[n0+1];
                    const float* d=D3[mt*2+nt];
                    const float vA0=d[0]+bv0, vA1=d[1]+bv1;
                    const float vB0=d[2]+bv0, vB1=d[3]+bv1;
                    if(vA0>bestA){bestA=vA0;nA=n0;}
                    if(vA1>bestA){bestA=vA1;nA=n0+1;}
                    if(vB0>bestB){bestB=vB0;nB=n0;}
                    if(vB1>bestB){bestB=vB1;nB=n0+1;}
                }
                #pragma unroll
                for(int m=1;m<=2;m<<=1){
                    const float ovA=__shfl_xor_sync(0xFFFFFFFFu,bestA,m);
                    const int   onA=__shfl_xor_sync(0xFFFFFFFFu,nA,m);
                    if(ovA>bestA||(ovA==bestA&&onA<nA)){bestA=ovA;nA=onA;}
                    const float ovB=__shfl_xor_sync(0xFFFFFFFFu,bestB,m);
                    const int   onB=__shfl_xor_sync(0xFFFFFFFFu,nB,m);
                    if(ovB>bestB||(ovB==bestB&&onB<nB)){bestB=ovB;nB=onB;}
                }
                if((lane&3)==0){
                    const int r=wm*32+mt*16+g;
                    spv[wn*128+r]=bestA;   spi[wn*128+r]=nA;
                    spv[wn*128+r+8]=bestB; spi[wn*128+r+8]=nB;
                }
            }
        }
        // ---- spill Dr (f32) into freed Y0 region (all warps) ----
        {
            float* dr=reinterpret_cast<float*>(smem+SM_DR);
            const int g=lane>>2, c2=2*(lane&3);
            #pragma unroll
            for(int mt=0;mt<2;++mt)
                #pragma unroll
                for(int nt=0;nt<2;++nt){
                    const int n0=wn*16+nt*8+c2;
                    const float* d=Dr[mt*2+nt];
                    *reinterpret_cast<float2*>(dr+(wm*32+mt*16+g)*DRS+n0)  =make_float2(d[0],d[1]);
                    *reinterpret_cast<float2*>(dr+(wm*32+mt*16+g+8)*DRS+n0)=make_float2(d[2],d[3]);
                }
        }
        __syncthreads();

        // ---- tail ----
        if(tid<128){
            const int px=tid, wc=w0+px;
            if(wc<Wd){
                const float v0=spv[px], v1=spv[128+px];
                const int   i0=spi[px], i1=spi[128+px];
                const int bk=(v1>v0)?i1:i0;     // classes in i0 < i1: tie -> lower ✓
                const float* dr=reinterpret_cast<const float*>(smem+SM_DR);
                const float2 dv=*reinterpret_cast<const float2*>(dr+px*DRS+2*bk);
                const float reg0=lrelu(dv.x+smf[SM_BR/4+2*bk]);
                const float reg1=lrelu(dv.y+smf[SM_BR/4+2*bk+1]);
                const int flat=h*K+bk;
                out[pix_base+wc]      =((float)flat+reg0)*inv_k;
                out[plane+pix_base+wc]=lrelu(reg1);
            }
        }
        __syncthreads();            // dr/spv reads done before next tile
    }
}

extern "C" void kernel_launch(void* const* d_in, const int* in_sizes, int n_in,
                              void* d_out, int out_size)
{
    const float* x =(const float*)d_in[0];
    const float* W1=(const float*)d_in[1];
    const float* b1=(const float*)d_in[2];
    const float* W2=(const float*)d_in[3];
    const float* b2=(const float*)d_in[4];
    const float* W3=(const float*)d_in[5];
    const float* b3=(const float*)d_in[6];
    const float* Wr=(const float*)d_in[7];
    const float* br=(const float*)d_in[8];
    float* out=(float*)d_out;

    cudaFuncSetAttribute(reg1stage_emu,
                         cudaFuncAttributeMaxDynamicSharedMemorySize, SMEM_BYTES);
    dim3 grid(H,Bn);
    reg1stage_emu<<<grid,TPB,SMEM_BYTES>>>(x,W1,b1,W2,b2,W3,b3,Wr,br,out);
}